// round 2
// baseline (speedup 1.0000x reference)
#include <cuda_runtime.h>

// Problem constants (fixed by setup_inputs): B=512 rows, K=T=2048 bits.
#define BB 512
#define TT 2048
#define LCHUNK 64
#define NCHUNK (TT / LCHUNK)   // 32
#define WARM 80                // warmup steps for chunked scans (path-merge window)
#define NEGF (-1e4f)
#define LCF 2.0f               // Lc = 2/sigma^2, sigma=1

// ---------------- scratch (static device arrays; no allocations) -------------
// All [T][B] column-major: warp lanes = consecutive b -> coalesced.
__device__ float  g_y1 [TT * BB];   // Lc * y1  (systematic)
__device__ float  g_y2 [TT * BB];   // Lc * y2  (parity 1)
__device__ float  g_y1i[TT * BB];   // Lc * y1 interleaved
__device__ float  g_y3 [TT * BB];   // Lc * y3  (parity 2)
__device__ float  g_La1[TT * BB];   // a-priori for decoder 1 (L_int)
__device__ float  g_La2[TT * BB];   // a-priori for decoder 2 (Le1 interleaved)
__device__ float  g_L2 [TT * BB];   // decoder-2 full LLR (last iteration)
__device__ float4 g_alpha[TT * BB]; // forward state metrics (pre-step), 16MB
__device__ int    g_inv[TT];        // inverse interleaver

// ---------------- init ------------------------------------------------------
__global__ void k_init_la() {
    int i = blockIdx.x * blockDim.x + threadIdx.x;
    if (i < TT * BB) g_La1[i] = 0.f;
}

__global__ void k_inv(const int* __restrict__ il) {
    int k = blockIdx.x * blockDim.x + threadIdx.x;
    if (k < TT) g_inv[il[k]] = k;
}

// ---------------- encode + channel -------------------------------------------
// RSC (7,5): par = u ^ s1 ; s1' = u ^ s1 ^ s2 ; s2' = s1.
// thread = (which encoder, row b). which=0: y1,y2 ; which=1: y1i,y3.
__global__ void k_encode(const int* __restrict__ x,
                         const float* __restrict__ n1,
                         const float* __restrict__ n2,
                         const float* __restrict__ n3,
                         const int* __restrict__ il) {
    int tid = blockIdx.x * blockDim.x + threadIdx.x;
    if (tid >= 2 * BB) return;
    int which = tid >> 9;      // tid / BB
    int b = tid & (BB - 1);
    int s1 = 0, s2 = 0;
    if (which == 0) {
        #pragma unroll 4
        for (int t = 0; t < TT; t++) {
            int u = x[b * TT + t];
            g_y1[t * BB + b] = LCF * (2.f * (float)u - 1.f + n1[b * TT + t]);
            int par = u ^ s1;
            int ns1 = u ^ s1 ^ s2; s2 = s1; s1 = ns1;
            g_y2[t * BB + b] = LCF * (2.f * (float)par - 1.f + n2[b * TT + t]);
        }
    } else {
        #pragma unroll 4
        for (int t = 0; t < TT; t++) {
            int j = il[t];
            int u = x[b * TT + j];
            g_y1i[t * BB + b] = LCF * (2.f * (float)u - 1.f + n1[b * TT + j]);
            int par = u ^ s1;
            int ns1 = u ^ s1 ^ s2; s2 = s1; s1 = ns1;
            g_y3[t * BB + b] = LCF * (2.f * (float)par - 1.f + n3[b * TT + t]);
        }
    }
}

// ---------------- forward (alpha) --------------------------------------------
// Trellis step (a0 kept at 0 by normalization; constant shifts cancel in LLR):
//   g11 = .5A + .5P, g10 = .5A - .5P, g00=-g11, g01=-g10
//   n0 = max(a0-g11, a1+g11); n1 = max(a2+g10, a3-g10)
//   n2 = max(a0+g11, a1-g11); n3 = max(a2-g10, a3+g10)
__global__ void k_fwd(int dec) {
    const float* __restrict__ ys = dec ? g_y1i : g_y1;
    const float* __restrict__ la = dec ? g_La2 : g_La1;
    const float* __restrict__ pp = dec ? g_y3  : g_y2;

    int tid = blockIdx.x * blockDim.x + threadIdx.x;
    int w = tid >> 5, lane = tid & 31;
    int chunk = w >> 4;                       // 16 warps per chunk (B/32)
    int b = ((w & 15) << 5) | lane;
    if (chunk >= NCHUNK) return;

    int t0 = chunk * LCHUNK;
    int ws = t0 - WARM;
    float a1, a2, a3;                          // a0 == 0 invariant
    if (ws <= 0) { ws = 0; a1 = a2 = a3 = NEGF; }   // exact initial condition
    else         { a1 = a2 = a3 = 0.f; }            // uniform warmup seed

    #pragma unroll 4
    for (int t = ws; t < t0; t++) {
        float A = ys[t * BB + b] + la[t * BB + b];
        float P = pp[t * BB + b];
        float g11 = 0.5f * A + 0.5f * P;
        float g10 = 0.5f * A - 0.5f * P;
        float n0 = fmaxf(-g11, a1 + g11);
        float m1 = fmaxf(a2 + g10, a3 - g10);
        float m2 = fmaxf( g11, a1 - g11);
        float m3 = fmaxf(a2 - g10, a3 + g10);
        a1 = m1 - n0; a2 = m2 - n0; a3 = m3 - n0;
    }
    #pragma unroll 4
    for (int t = t0; t < t0 + LCHUNK; t++) {
        g_alpha[t * BB + b] = make_float4(0.f, a1, a2, a3);  // pre-step alpha_t
        float A = ys[t * BB + b] + la[t * BB + b];
        float P = pp[t * BB + b];
        float g11 = 0.5f * A + 0.5f * P;
        float g10 = 0.5f * A - 0.5f * P;
        float n0 = fmaxf(-g11, a1 + g11);
        float m1 = fmaxf(a2 + g10, a3 - g10);
        float m2 = fmaxf( g11, a1 - g11);
        float m3 = fmaxf(a2 - g10, a3 + g10);
        a1 = m1 - n0; a2 = m2 - n0; a3 = m3 - n0;
    }
}

// ---------------- backward (beta) + LLR + extrinsic + scatter -----------------
// Beta step:
//   n0 = max(b0-g11, b2+g11); n1 = max(b2-g11, b0+g11)
//   n2 = max(b3-g10, b1+g10); n3 = max(b1-g10, b3+g10)      (b0 kept 0)
// LLR_t uses beta_{t+1} (current beta before applying gamma_t) and alpha_t:
//   m1 = max(a0+g11+b2, a1+g11+b0, a2+g10+b1, a3+g10+b3)
//   m0 = max(a0-g11+b0, a1-g11+b2, a2-g10+b3, a3-g10+b1)
__global__ void k_bwd(int dec, const int* __restrict__ il) {
    const float* __restrict__ ys = dec ? g_y1i : g_y1;
    const float* __restrict__ la = dec ? g_La2 : g_La1;
    const float* __restrict__ pp = dec ? g_y3  : g_y2;
    float* __restrict__ lanext   = dec ? g_La1 : g_La2;

    int tid = blockIdx.x * blockDim.x + threadIdx.x;
    int w = tid >> 5, lane = tid & 31;
    int chunk = w >> 4;
    int b = ((w & 15) << 5) | lane;
    if (chunk >= NCHUNK) return;

    int t0 = chunk * LCHUNK;
    int t1 = t0 + LCHUNK;
    int we = t1 + WARM;
    if (we > TT) we = TT;                    // uniform end == exact beta_end
    float b1, b2, b3;                        // b0 == 0 invariant
    b1 = b2 = b3 = 0.f;

    #pragma unroll 4
    for (int t = we - 1; t >= t1; t--) {
        float A = ys[t * BB + b] + la[t * BB + b];
        float P = pp[t * BB + b];
        float g11 = 0.5f * A + 0.5f * P;
        float g10 = 0.5f * A - 0.5f * P;
        float n0 = fmaxf(-g11, b2 + g11);
        float m1 = fmaxf(b2 - g11,  g11);
        float m2 = fmaxf(b3 - g10, b1 + g10);
        float m3 = fmaxf(b1 - g10, b3 + g10);
        b1 = m1 - n0; b2 = m2 - n0; b3 = m3 - n0;
    }
    #pragma unroll 2
    for (int t = t1 - 1; t >= t0; t--) {
        float4 al = g_alpha[t * BB + b];
        float A = ys[t * BB + b] + la[t * BB + b];
        float P = pp[t * BB + b];
        float g11 = 0.5f * A + 0.5f * P;
        float g10 = 0.5f * A - 0.5f * P;

        // LLR with beta_{t+1}
        float u1 = fmaxf(fmaxf(al.x + g11 + b2, al.y + g11),
                         fmaxf(al.z + g10 + b1, al.w + g10 + b3));
        float u0 = fmaxf(fmaxf(al.x - g11,      al.y - g11 + b2),
                         fmaxf(al.z - g10 + b3, al.w - g10 + b1));
        float llr = u1 - u0;
        float le = llr - A;                  // extrinsic = L - Lc*y - La

        int kdst = dec ? il[t] : g_inv[t];
        lanext[kdst * BB + b] = le;          // fused (de)interleave scatter
        if (dec) g_L2[t * BB + b] = llr;

        // beta update with gamma_t
        float n0 = fmaxf(-g11, b2 + g11);
        float m1 = fmaxf(b2 - g11,  g11);
        float m2 = fmaxf(b3 - g10, b1 + g10);
        float m3 = fmaxf(b1 - g10, b3 + g10);
        b1 = m1 - n0; b2 = m2 - n0; b3 = m3 - n0;
    }
}

// ---------------- final deinterleave + transpose to [B,K] ---------------------
__global__ void k_out(float* __restrict__ out) {
    __shared__ float tile[32][33];
    int j0 = blockIdx.x * 32, b0 = blockIdx.y * 32;
    int tx = threadIdx.x, ty = threadIdx.y;
    int j = j0 + ty;
    tile[ty][tx] = g_L2[g_inv[j] * BB + b0 + tx];   // coalesced in b
    __syncthreads();
    out[(b0 + ty) * TT + j0 + tx] = tile[tx][ty];   // coalesced in j
}

// ---------------- launch ------------------------------------------------------
extern "C" void kernel_launch(void* const* d_in, const int* in_sizes, int n_in,
                              void* d_out, int out_size) {
    const int*   x  = (const int*)d_in[0];
    const float* n1 = (const float*)d_in[1];
    const float* n2 = (const float*)d_in[2];
    const float* n3 = (const float*)d_in[3];
    const int*   il = (const int*)d_in[4];
    float* out = (float*)d_out;

    k_init_la<<<(TT * BB + 255) / 256, 256>>>();
    k_inv<<<(TT + 255) / 256, 256>>>(il);
    k_encode<<<(2 * BB + 127) / 128, 128>>>(x, n1, n2, n3, il);

    const int scan_blocks = (BB * NCHUNK) / 128;   // 128 blocks of 128 threads
    for (int it = 0; it < 6; it++) {
        k_fwd<<<scan_blocks, 128>>>(0);
        k_bwd<<<scan_blocks, 128>>>(0, il);
        k_fwd<<<scan_blocks, 128>>>(1);
        k_bwd<<<scan_blocks, 128>>>(1, il);
    }
    k_out<<<dim3(TT / 32, BB / 32), dim3(32, 32)>>>(out);
}

// round 3
// speedup vs baseline: 3.5053x; 3.5053x over previous
#include <cuda_runtime.h>

// Problem constants (fixed by setup_inputs): B=512 rows, K=T=2048 bits.
#define BB 512
#define TT 2048
#define L 16               // BCJR chunk length
#define NC (TT / L)        // 128 chunks
#define W 64               // warmup (path-merge) window
#define NEGF (-1e4f)
// encoder chunking
#define ECH 64
#define ENC (TT / ECH)     // 32 encoder chunks

// ---------------- scratch (static device arrays; no allocations) -------------
// All [T][B] column-major: warp lanes = consecutive b -> coalesced.
// G.x = A' = y_sys + La/2 (note 0.5*Lc == 1), G.y = P' = y_par.
__device__ float2 g_G1[TT * BB];   // decoder-1 branch inputs
__device__ float2 g_G2[TT * BB];   // decoder-2 branch inputs
__device__ float  g_h1 [TT * BB];  // y1  (static systematic, col-major)
__device__ float  g_h1i[TT * BB];  // y1 interleaved (static)
__device__ float  g_n2c[TT * BB];  // n2 col-major
__device__ float  g_n3c[TT * BB];  // n3 col-major
__device__ float  g_L2 [TT * BB];  // decoder-2 full LLR
__device__ unsigned char g_xc[TT * BB];  // bits col-major
__device__ int    g_inv[TT];       // inverse interleaver
__device__ unsigned char g_dc[2 * ENC * BB];  // encoder chunk offsets
__device__ unsigned char g_ss[2 * ENC * BB];  // encoder chunk start states

// ---------------- init ------------------------------------------------------
__global__ void k_inv(const int* __restrict__ il) {
    int k = blockIdx.x * blockDim.x + threadIdx.x;
    if (k < TT) g_inv[il[k]] = k;
}

// ---------------- transpose inputs to [T][B] ---------------------------------
__global__ void k_tp(const int* __restrict__ x, const float* __restrict__ n1,
                     const float* __restrict__ n2, const float* __restrict__ n3) {
    __shared__ int   tx_[32][33];
    __shared__ float t1_[32][33];
    __shared__ float t2_[32][33];
    __shared__ float t3_[32][33];
    int t0 = blockIdx.x * 32, b0 = blockIdx.y * 32;
    int tx = threadIdx.x, ty = threadIdx.y;
    int src = (b0 + ty) * TT + t0 + tx;          // coalesced along t
    tx_[ty][tx] = x[src];
    t1_[ty][tx] = n1[src];
    t2_[ty][tx] = n2[src];
    t3_[ty][tx] = n3[src];
    __syncthreads();
    int dst = (t0 + ty) * BB + b0 + tx;          // coalesced along b
    int xv = tx_[tx][ty];
    g_xc [dst] = (unsigned char)xv;
    g_h1 [dst] = 2.f * (float)xv - 1.f + t1_[tx][ty];   // y1 = c1 + n1
    g_n2c[dst] = t2_[tx][ty];
    g_n3c[dst] = t3_[tx][ty];
}

// ---------------- chunk-parallel RSC encode ----------------------------------
// RSC (7,5): par = u ^ s1 ; s1' = u ^ s1 ^ s2 ; s2' = s1.  State map over GF(2)
// is affine: s_{t+L} = F^L s_t + d_chunk, with F = [[1,1],[1,0]], F^3 = I, so
// F^64 = F.  Phase 1: d_chunk from zero start.  Phase 2: serial compose (32
// steps).  Phase 3: emit parities from exact start states.
__global__ void k_enc1(const int* __restrict__ il) {
    int tid = blockIdx.x * blockDim.x + threadIdx.x;
    if (tid >= 2 * ENC * BB) return;
    int b = tid & (BB - 1);
    int c = (tid >> 9) & (ENC - 1);
    int e = tid >> 14;
    int s1 = 0, s2 = 0;
    int base = c * ECH;
    for (int k = 0; k < ECH; k++) {
        int t = base + k;
        int row = e ? il[t] : t;                 // il[t] warp-uniform -> coalesced
        int u = (int)g_xc[row * BB + b];
        int ns1 = u ^ s1 ^ s2; s2 = s1; s1 = ns1;
    }
    g_dc[tid] = (unsigned char)((s1 << 1) | s2);
}

__global__ void k_enc2() {
    int tid = blockIdx.x * blockDim.x + threadIdx.x;
    if (tid >= 2 * BB) return;
    int b = tid & (BB - 1);
    int e = tid >> 9;
    int s1 = 0, s2 = 0;
    for (int c = 0; c < ENC; c++) {
        int idx = (e * ENC + c) * BB + b;
        g_ss[idx] = (unsigned char)((s1 << 1) | s2);
        int d = (int)g_dc[idx];
        int ns1 = s1 ^ s2 ^ (d >> 1);            // F * s + d   (F^64 = F)
        int ns2 = s1 ^ (d & 1);
        s1 = ns1; s2 = ns2;
    }
}

__global__ void k_enc3(const int* __restrict__ il) {
    int tid = blockIdx.x * blockDim.x + threadIdx.x;
    if (tid >= 2 * ENC * BB) return;
    int b = tid & (BB - 1);
    int c = (tid >> 9) & (ENC - 1);
    int e = tid >> 14;
    int s = (int)g_ss[tid];
    int s1 = s >> 1, s2 = s & 1;
    int base = c * ECH;
    if (e == 0) {
        for (int k = 0; k < ECH; k++) {
            int t = base + k;
            int i = t * BB + b;
            int u = (int)g_xc[i];
            int p = u ^ s1;
            int ns1 = u ^ s1 ^ s2; s2 = s1; s1 = ns1;
            g_G1[i] = make_float2(g_h1[i], 2.f * (float)p - 1.f + g_n2c[i]);
        }
    } else {
        for (int k = 0; k < ECH; k++) {
            int t = base + k;
            int i = t * BB + b;
            int row = il[t];
            int u = (int)g_xc[row * BB + b];
            float h1i = g_h1[row * BB + b];
            g_h1i[i] = h1i;
            int p = u ^ s1;
            int ns1 = u ^ s1 ^ s2; s2 = s1; s1 = ns1;
            g_G2[i] = make_float2(h1i, 2.f * (float)p - 1.f + g_n3c[i]);
        }
    }
}

// ---------------- fused BCJR: forward + backward + LLR + scatter --------------
// Unnormalized max-plus recursion (shift-invariant; renorm every 16 steps).
//   g11 = A' + P', g10 = A' - P'
// forward:  n0=max(a0-g11,a1+g11) n1=max(a2+g10,a3-g10)
//           n2=max(a0+g11,a1-g11) n3=max(a2-g10,a3+g10)
// backward: n0=max(b0-g11,b2+g11) n1=max(b0+g11,b2-g11)
//           n2=max(b1+g10,b3-g10) n3=max(b1-g10,b3+g10)
#define FSTEP(T_) do { \
    float2 v = G[(T_) * BB + b]; \
    float g11 = v.x + v.y; float g10 = v.x - v.y; \
    float m0 = fmaxf(a0 - g11, a1 + g11); \
    float m1 = fmaxf(a2 + g10, a3 - g10); \
    float m2 = fmaxf(a0 + g11, a1 - g11); \
    float m3 = fmaxf(a2 - g10, a3 + g10); \
    a0 = m0; a1 = m1; a2 = m2; a3 = m3; } while (0)

#define BSTEP_G(g11, g10) do { \
    float m0 = fmaxf(b0 - (g11), b2 + (g11)); \
    float m1 = fmaxf(b0 + (g11), b2 - (g11)); \
    float m2 = fmaxf(b1 + (g10), b3 - (g10)); \
    float m3 = fmaxf(b1 - (g10), b3 + (g10)); \
    b0 = m0; b1 = m1; b2 = m2; b3 = m3; } while (0)

__global__ __launch_bounds__(128) void k_bcjr(int dec, const int* __restrict__ il) {
    __shared__ float4 sA[L * 128];               // 32 KB: chunk-local alpha
    const float2* __restrict__ G = dec ? g_G2 : g_G1;
    int tid = threadIdx.x;
    int chunk = blockIdx.y;
    int b = (blockIdx.x << 7) + tid;
    int t0 = chunk * L, t1 = t0 + L;

    // ---- forward (warmup + chunk, alpha to shared) ----
    float a0, a1, a2, a3;
    int ws = t0 - W;
    if (ws <= 0) { ws = 0; a0 = 0.f; a1 = a2 = a3 = NEGF; }  // exact start
    else         { a0 = a1 = a2 = a3 = 0.f; }                // merged warmup
    for (int tb = ws; tb < t0; tb += 16) {
        #pragma unroll
        for (int k = 0; k < 16; k++) FSTEP(tb + k);
        a1 -= a0; a2 -= a0; a3 -= a0; a0 = 0.f;
    }
    #pragma unroll
    for (int k = 0; k < 16; k++) {
        sA[k * 128 + tid] = make_float4(a0, a1, a2, a3);     // pre-step alpha_t
        FSTEP(t0 + k);
    }

    // ---- backward (warmup + chunk with LLR/extrinsic) ----
    float b0 = 0.f, b1 = 0.f, b2 = 0.f, b3 = 0.f;            // uniform (exact at TT)
    int we = t1 + W; if (we > TT) we = TT;
    for (int tb = we; tb > t1; tb -= 16) {
        #pragma unroll
        for (int k = 1; k <= 16; k++) {
            int t = tb - k;
            float2 v = G[t * BB + b];
            float g11 = v.x + v.y, g10 = v.x - v.y;
            BSTEP_G(g11, g10);
        }
        b1 -= b0; b2 -= b0; b3 -= b0; b0 = 0.f;
    }
    #pragma unroll
    for (int k = 15; k >= 0; k--) {
        int t = t0 + k;
        float4 al = sA[k * 128 + tid];
        float2 v = G[t * BB + b];
        float g11 = v.x + v.y, g10 = v.x - v.y;
        // LLR with alpha_t, gamma_t, beta_{t+1}
        float u1 = fmaxf(fmaxf(al.x + g11 + b2, al.y + g11 + b0),
                         fmaxf(al.z + g10 + b1, al.w + g10 + b3));
        float u0 = fmaxf(fmaxf(al.x - g11 + b0, al.y - g11 + b2),
                         fmaxf(al.z - g10 + b3, al.w - g10 + b1));
        float llr = u1 - u0;
        float lh  = 0.5f * llr - v.x;            // 0.5*Le (Le = llr - 2*A')
        if (dec == 0) {
            int kd = g_inv[t];                   // warp-uniform -> coalesced
            g_G2[kd * BB + b].x = lh + g_h1[t * BB + b];     // A2' at interleaved pos
        } else {
            int kd = il[t];
            g_G1[kd * BB + b].x = lh + g_h1i[t * BB + b];    // A1' deinterleaved
            g_L2[t * BB + b] = llr;
        }
        BSTEP_G(g11, g10);
    }
}

// ---------------- final deinterleave + transpose to [B,K] ---------------------
__global__ void k_out(float* __restrict__ out) {
    __shared__ float tile[32][33];
    int j0 = blockIdx.x * 32, b0 = blockIdx.y * 32;
    int tx = threadIdx.x, ty = threadIdx.y;
    tile[ty][tx] = g_L2[g_inv[j0 + ty] * BB + b0 + tx];      // coalesced in b
    __syncthreads();
    out[(b0 + ty) * TT + j0 + tx] = tile[tx][ty];            // coalesced in j
}

// ---------------- launch ------------------------------------------------------
extern "C" void kernel_launch(void* const* d_in, const int* in_sizes, int n_in,
                              void* d_out, int out_size) {
    const int*   x  = (const int*)d_in[0];
    const float* n1 = (const float*)d_in[1];
    const float* n2 = (const float*)d_in[2];
    const float* n3 = (const float*)d_in[3];
    const int*   il = (const int*)d_in[4];
    float* out = (float*)d_out;

    k_inv<<<(TT + 255) / 256, 256>>>(il);
    k_tp<<<dim3(TT / 32, BB / 32), dim3(32, 32)>>>(x, n1, n2, n3);
    k_enc1<<<(2 * ENC * BB + 255) / 256, 256>>>(il);
    k_enc2<<<(2 * BB + 255) / 256, 256>>>();
    k_enc3<<<(2 * ENC * BB + 255) / 256, 256>>>(il);

    for (int it = 0; it < 6; it++) {
        k_bcjr<<<dim3(BB / 128, NC), 128>>>(0, il);
        k_bcjr<<<dim3(BB / 128, NC), 128>>>(1, il);
    }
    k_out<<<dim3(TT / 32, BB / 32), dim3(32, 32)>>>(out);
}